// round 1
// baseline (speedup 1.0000x reference)
#include <cuda_runtime.h>
#include <cstdint>

#define NUM_RELS 500
#define ENT_DIM  128

// Per-relation precomputed scalars: [S_pp, S_pr, S_p, S_rr, S_r]
__device__ float g_rel_c[NUM_RELS * 5];

__device__ __forceinline__ float warp_sum(float v) {
    #pragma unroll
    for (int o = 16; o > 0; o >>= 1)
        v += __shfl_xor_sync(0xFFFFFFFFu, v, o);
    return v;
}

// One warp per relation: 32 lanes x float4 = 128 floats per vector.
__global__ void rel_precompute_kernel(const float* __restrict__ rel,
                                      const float* __restrict__ rel_p) {
    int warp = (blockIdx.x * blockDim.x + threadIdx.x) >> 5;
    int lane = threadIdx.x & 31;
    if (warp >= NUM_RELS) return;

    const float4* r4 = reinterpret_cast<const float4*>(rel   + (size_t)warp * ENT_DIM);
    const float4* p4 = reinterpret_cast<const float4*>(rel_p + (size_t)warp * ENT_DIM);
    float4 q = r4[lane];
    float4 p = p4[lane];

    float s_pp = p.x*p.x + p.y*p.y + p.z*p.z + p.w*p.w;
    float s_pr = p.x*q.x + p.y*q.y + p.z*q.z + p.w*q.w;
    float s_p  = p.x + p.y + p.z + p.w;
    float s_rr = q.x*q.x + q.y*q.y + q.z*q.z + q.w*q.w;
    float s_r  = q.x + q.y + q.z + q.w;

    s_pp = warp_sum(s_pp);
    s_pr = warp_sum(s_pr);
    s_p  = warp_sum(s_p);
    s_rr = warp_sum(s_rr);
    s_r  = warp_sum(s_r);

    if (lane == 0) {
        float* c = g_rel_c + (size_t)warp * 5;
        c[0] = s_pp; c[1] = s_pr; c[2] = s_p; c[3] = s_rr; c[4] = s_r;
    }
}

// One warp per batch row.
__global__ __launch_bounds__(256)
void transd_score_kernel(const float* __restrict__ head_emb,
                         const float* __restrict__ head_emb_p,
                         const float* __restrict__ tail_emb,
                         const float* __restrict__ tail_emb_p,
                         const int*   __restrict__ head_idx,
                         const int*   __restrict__ tail_idx,
                         const int*   __restrict__ rel_idx,
                         float* __restrict__ out,
                         int B) {
    int warp = (blockIdx.x * blockDim.x + threadIdx.x) >> 5;
    int lane = threadIdx.x & 31;
    if (warp >= B) return;

    int hi = head_idx[warp];
    int ti = tail_idx[warp];
    int ri = rel_idx[warp];

    const float4* h4  = reinterpret_cast<const float4*>(head_emb   + (size_t)hi * ENT_DIM);
    const float4* hp4 = reinterpret_cast<const float4*>(head_emb_p + (size_t)hi * ENT_DIM);
    const float4* t4  = reinterpret_cast<const float4*>(tail_emb   + (size_t)ti * ENT_DIM);
    const float4* tp4 = reinterpret_cast<const float4*>(tail_emb_p + (size_t)ti * ENT_DIM);

    float4 vh  = h4[lane];
    float4 vhp = hp4[lane];
    float4 vt  = t4[lane];
    float4 vtp = tp4[lane];

    // a = h_p.h - t_p.t ;  b = sum(h) - sum(t)   (per-lane partials)
    float a = vhp.x*vh.x + vhp.y*vh.y + vhp.z*vh.z + vhp.w*vh.w
            - (vtp.x*vt.x + vtp.y*vt.y + vtp.z*vt.z + vtp.w*vt.w);
    float b = (vh.x + vh.y + vh.z + vh.w) - (vt.x + vt.y + vt.z + vt.w);

    a = warp_sum(a);
    b = warp_sum(b);

    if (lane == 0) {
        const float* c = g_rel_c + (size_t)ri * 5;
        float s_pp = c[0], s_pr = c[1], s_p = c[2], s_rr = c[3], s_r = c[4];
        // score = sum_j (a*r_p[j] + r[j] + b)^2
        //       = a^2*S_pp + 2a*S_pr + 2ab*S_p + S_rr + 2b*S_r + D*b^2
        float score = a*a*s_pp + 2.0f*a*s_pr + 2.0f*a*b*s_p
                    + s_rr + 2.0f*b*s_r + (float)ENT_DIM * b*b;
        out[warp] = score;
    }
}

extern "C" void kernel_launch(void* const* d_in, const int* in_sizes, int n_in,
                              void* d_out, int out_size) {
    const float* head_emb   = (const float*)d_in[0];
    const float* head_emb_p = (const float*)d_in[1];
    const float* tail_emb   = (const float*)d_in[2];
    const float* tail_emb_p = (const float*)d_in[3];
    const float* rel_emb    = (const float*)d_in[4];
    const float* rel_emb_p  = (const float*)d_in[5];
    const int*   head_idx   = (const int*)d_in[6];
    const int*   tail_idx   = (const int*)d_in[7];
    const int*   rel_idx    = (const int*)d_in[8];
    float* out = (float*)d_out;

    int B = in_sizes[6];  // number of head indices == batch size

    // Precompute 5 scalars per relation (500 warps).
    {
        int threads = 256;                       // 8 warps/block
        int blocks = (NUM_RELS * 32 + threads - 1) / threads;
        rel_precompute_kernel<<<blocks, threads>>>(rel_emb, rel_emb_p);
    }

    // One warp per row.
    {
        int threads = 256;                       // 8 rows per block
        int blocks = (B + 7) / 8;
        transd_score_kernel<<<blocks, threads>>>(head_emb, head_emb_p,
                                                 tail_emb, tail_emb_p,
                                                 head_idx, tail_idx, rel_idx,
                                                 out, B);
    }
}

// round 2
// speedup vs baseline: 1.7938x; 1.7938x over previous
#include <cuda_runtime.h>
#include <cstdint>

#define NUM_RELS 500
#define N_NODES  200000
#define ENT_DIM  128

// Per-relation precomputed scalars: [S_pp, S_pr, S_p, S_rr, S_r]
__device__ float g_rel_c[NUM_RELS * 5];
// Per-node precomputed scalars: x = emb_p . emb,  y = sum(emb)
__device__ float2 g_node_h[N_NODES];
__device__ float2 g_node_t[N_NODES];

__device__ __forceinline__ float warp_sum(float v) {
    #pragma unroll
    for (int o = 16; o > 0; o >>= 1)
        v += __shfl_xor_sync(0xFFFFFFFFu, v, o);
    return v;
}

// One warp per relation.
__global__ void rel_precompute_kernel(const float* __restrict__ rel,
                                      const float* __restrict__ rel_p) {
    int warp = (blockIdx.x * blockDim.x + threadIdx.x) >> 5;
    int lane = threadIdx.x & 31;
    if (warp >= NUM_RELS) return;

    const float4* r4 = reinterpret_cast<const float4*>(rel   + (size_t)warp * ENT_DIM);
    const float4* p4 = reinterpret_cast<const float4*>(rel_p + (size_t)warp * ENT_DIM);
    float4 q = r4[lane];
    float4 p = p4[lane];

    float s_pp = p.x*p.x + p.y*p.y + p.z*p.z + p.w*p.w;
    float s_pr = p.x*q.x + p.y*q.y + p.z*q.z + p.w*q.w;
    float s_p  = p.x + p.y + p.z + p.w;
    float s_rr = q.x*q.x + q.y*q.y + q.z*q.z + q.w*q.w;
    float s_r  = q.x + q.y + q.z + q.w;

    s_pp = warp_sum(s_pp);
    s_pr = warp_sum(s_pr);
    s_p  = warp_sum(s_p);
    s_rr = warp_sum(s_rr);
    s_r  = warp_sum(s_r);

    if (lane == 0) {
        float* c = g_rel_c + (size_t)warp * 5;
        c[0] = s_pp; c[1] = s_pr; c[2] = s_p; c[3] = s_rr; c[4] = s_r;
    }
}

// One warp per (node, side). Streams both entity-table pairs exactly once.
// side 0: head tables -> g_node_h ; side 1: tail tables -> g_node_t
__global__ __launch_bounds__(256)
void node_precompute_kernel(const float* __restrict__ head_emb,
                            const float* __restrict__ head_emb_p,
                            const float* __restrict__ tail_emb,
                            const float* __restrict__ tail_emb_p) {
    int warp = (blockIdx.x * blockDim.x + threadIdx.x) >> 5;
    int lane = threadIdx.x & 31;
    if (warp >= 2 * N_NODES) return;

    int side = (warp >= N_NODES) ? 1 : 0;
    int node = side ? (warp - N_NODES) : warp;

    const float* emb   = side ? tail_emb   : head_emb;
    const float* emb_p = side ? tail_emb_p : head_emb_p;

    const float4* e4 = reinterpret_cast<const float4*>(emb   + (size_t)node * ENT_DIM);
    const float4* p4 = reinterpret_cast<const float4*>(emb_p + (size_t)node * ENT_DIM);
    float4 e = e4[lane];
    float4 p = p4[lane];

    float a = p.x*e.x + p.y*e.y + p.z*e.z + p.w*e.w;   // emb_p . emb partial
    float b = e.x + e.y + e.z + e.w;                   // sum(emb) partial

    a = warp_sum(a);
    b = warp_sum(b);

    if (lane == 0) {
        float2 v = make_float2(a, b);
        if (side) g_node_t[node] = v;
        else      g_node_h[node] = v;
    }
}

// One thread per batch row; all tables involved are L2-resident.
__global__ __launch_bounds__(256)
void transd_score_kernel(const int* __restrict__ head_idx,
                         const int* __restrict__ tail_idx,
                         const int* __restrict__ rel_idx,
                         float* __restrict__ out,
                         int B) {
    int i = blockIdx.x * blockDim.x + threadIdx.x;
    if (i >= B) return;

    int hi = head_idx[i];
    int ti = tail_idx[i];
    int ri = rel_idx[i];

    float2 hc = g_node_h[hi];
    float2 tc = g_node_t[ti];
    float a = hc.x - tc.x;   // h_p.h - t_p.t
    float b = hc.y - tc.y;   // sum(h) - sum(t)

    const float* c = g_rel_c + (size_t)ri * 5;
    float s_pp = __ldg(c + 0);
    float s_pr = __ldg(c + 1);
    float s_p  = __ldg(c + 2);
    float s_rr = __ldg(c + 3);
    float s_r  = __ldg(c + 4);

    // score = sum_j (a*r_p[j] + r[j] + b)^2
    //       = a^2*S_pp + 2a*S_pr + 2ab*S_p + S_rr + 2b*S_r + D*b^2
    out[i] = a*a*s_pp + 2.0f*a*s_pr + 2.0f*a*b*s_p
           + s_rr + 2.0f*b*s_r + (float)ENT_DIM * b*b;
}

extern "C" void kernel_launch(void* const* d_in, const int* in_sizes, int n_in,
                              void* d_out, int out_size) {
    const float* head_emb   = (const float*)d_in[0];
    const float* head_emb_p = (const float*)d_in[1];
    const float* tail_emb   = (const float*)d_in[2];
    const float* tail_emb_p = (const float*)d_in[3];
    const float* rel_emb    = (const float*)d_in[4];
    const float* rel_emb_p  = (const float*)d_in[5];
    const int*   head_idx   = (const int*)d_in[6];
    const int*   tail_idx   = (const int*)d_in[7];
    const int*   rel_idx    = (const int*)d_in[8];
    float* out = (float*)d_out;

    int B = in_sizes[6];

    // Per-relation scalars (500 warps, trivial).
    {
        int threads = 256;
        int blocks = (NUM_RELS * 32 + threads - 1) / threads;
        rel_precompute_kernel<<<blocks, threads>>>(rel_emb, rel_emb_p);
    }

    // Per-node scalars: stream all four entity tables once (410 MB).
    {
        int threads = 256;                          // 8 warps/block
        long long warps = 2LL * N_NODES;
        int blocks = (int)((warps * 32 + threads - 1) / threads);
        node_precompute_kernel<<<blocks, threads>>>(head_emb, head_emb_p,
                                                    tail_emb, tail_emb_p);
    }

    // Closed-form score, one thread per row.
    {
        int threads = 256;
        int blocks = (B + threads - 1) / threads;
        transd_score_kernel<<<blocks, threads>>>(head_idx, tail_idx, rel_idx,
                                                 out, B);
    }
}

// round 3
// speedup vs baseline: 1.9060x; 1.0625x over previous
#include <cuda_runtime.h>
#include <cstdint>

#define NUM_RELS 500
#define N_NODES  200000
#define ENT_DIM  128

// Per-relation scalars padded to 8 floats: [S_pp, S_pr, S_p, S_rr, S_r, 0,0,0]
__device__ float4 g_rel_c[NUM_RELS * 2];
// Per-node scalars: x = emb_p . emb,  y = sum(emb)
__device__ float2 g_node_h[N_NODES];
__device__ float2 g_node_t[N_NODES];

__device__ __forceinline__ float warp_sum(float v) {
    #pragma unroll
    for (int o = 16; o > 0; o >>= 1)
        v += __shfl_xor_sync(0xFFFFFFFFu, v, o);
    return v;
}

// Fused precompute:
//   warp <  N_NODES           : per-node scalars for all 4 entity tables
//   warp in [N_NODES, +RELS)  : per-relation scalars
__global__ __launch_bounds__(256)
void precompute_kernel(const float* __restrict__ head_emb,
                       const float* __restrict__ head_emb_p,
                       const float* __restrict__ tail_emb,
                       const float* __restrict__ tail_emb_p,
                       const float* __restrict__ rel_emb,
                       const float* __restrict__ rel_emb_p) {
    int warp = (blockIdx.x * blockDim.x + threadIdx.x) >> 5;
    int lane = threadIdx.x & 31;

    if (warp < N_NODES) {
        int node = warp;
        const float4* h4  = reinterpret_cast<const float4*>(head_emb   + (size_t)node * ENT_DIM);
        const float4* hp4 = reinterpret_cast<const float4*>(head_emb_p + (size_t)node * ENT_DIM);
        const float4* t4  = reinterpret_cast<const float4*>(tail_emb   + (size_t)node * ENT_DIM);
        const float4* tp4 = reinterpret_cast<const float4*>(tail_emb_p + (size_t)node * ENT_DIM);

        float4 h  = h4[lane];
        float4 hp = hp4[lane];
        float4 t  = t4[lane];
        float4 tp = tp4[lane];

        float ah = hp.x*h.x + hp.y*h.y + hp.z*h.z + hp.w*h.w;
        float bh = h.x + h.y + h.z + h.w;
        float at = tp.x*t.x + tp.y*t.y + tp.z*t.z + tp.w*t.w;
        float bt = t.x + t.y + t.z + t.w;

        ah = warp_sum(ah);
        bh = warp_sum(bh);
        at = warp_sum(at);
        bt = warp_sum(bt);

        if (lane == 0) {
            g_node_h[node] = make_float2(ah, bh);
            g_node_t[node] = make_float2(at, bt);
        }
    } else if (warp < N_NODES + NUM_RELS) {
        int rel = warp - N_NODES;
        const float4* r4 = reinterpret_cast<const float4*>(rel_emb   + (size_t)rel * ENT_DIM);
        const float4* p4 = reinterpret_cast<const float4*>(rel_emb_p + (size_t)rel * ENT_DIM);
        float4 q = r4[lane];
        float4 p = p4[lane];

        float s_pp = p.x*p.x + p.y*p.y + p.z*p.z + p.w*p.w;
        float s_pr = p.x*q.x + p.y*q.y + p.z*q.z + p.w*q.w;
        float s_p  = p.x + p.y + p.z + p.w;
        float s_rr = q.x*q.x + q.y*q.y + q.z*q.z + q.w*q.w;
        float s_r  = q.x + q.y + q.z + q.w;

        s_pp = warp_sum(s_pp);
        s_pr = warp_sum(s_pr);
        s_p  = warp_sum(s_p);
        s_rr = warp_sum(s_rr);
        s_r  = warp_sum(s_r);

        if (lane == 0) {
            g_rel_c[rel * 2 + 0] = make_float4(s_pp, s_pr, s_p, s_rr);
            g_rel_c[rel * 2 + 1] = make_float4(s_r, 0.0f, 0.0f, 0.0f);
        }
    }
}

// One thread per batch row; node/rel scalar tables are L2/L1-resident.
__global__ __launch_bounds__(256)
void transd_score_kernel(const int* __restrict__ head_idx,
                         const int* __restrict__ tail_idx,
                         const int* __restrict__ rel_idx,
                         float* __restrict__ out,
                         int B) {
    int i = blockIdx.x * blockDim.x + threadIdx.x;
    if (i >= B) return;

    int hi = head_idx[i];
    int ti = tail_idx[i];
    int ri = rel_idx[i];

    float2 hc = g_node_h[hi];
    float2 tc = g_node_t[ti];
    float4 c0 = g_rel_c[ri * 2 + 0];
    float4 c1 = g_rel_c[ri * 2 + 1];

    float a = hc.x - tc.x;   // h_p.h - t_p.t
    float b = hc.y - tc.y;   // sum(h) - sum(t)

    // score = sum_j (a*r_p[j] + r[j] + b)^2
    //       = a^2*S_pp + 2a*S_pr + 2ab*S_p + S_rr + 2b*S_r + D*b^2
    out[i] = a*a*c0.x + 2.0f*a*c0.y + 2.0f*a*b*c0.z
           + c0.w + 2.0f*b*c1.x + (float)ENT_DIM * b*b;
}

extern "C" void kernel_launch(void* const* d_in, const int* in_sizes, int n_in,
                              void* d_out, int out_size) {
    const float* head_emb   = (const float*)d_in[0];
    const float* head_emb_p = (const float*)d_in[1];
    const float* tail_emb   = (const float*)d_in[2];
    const float* tail_emb_p = (const float*)d_in[3];
    const float* rel_emb    = (const float*)d_in[4];
    const float* rel_emb_p  = (const float*)d_in[5];
    const int*   head_idx   = (const int*)d_in[6];
    const int*   tail_idx   = (const int*)d_in[7];
    const int*   rel_idx    = (const int*)d_in[8];
    float* out = (float*)d_out;

    int B = in_sizes[6];

    // Fused per-node + per-relation precompute (streams all tables once).
    {
        int threads = 256;                 // 8 warps/block
        long long warps = (long long)N_NODES + NUM_RELS;
        int blocks = (int)((warps * 32 + threads - 1) / threads);
        precompute_kernel<<<blocks, threads>>>(head_emb, head_emb_p,
                                               tail_emb, tail_emb_p,
                                               rel_emb, rel_emb_p);
    }

    // Closed-form score, one thread per row.
    {
        int threads = 256;
        int blocks = (B + threads - 1) / threads;
        transd_score_kernel<<<blocks, threads>>>(head_idx, tail_idx, rel_idx,
                                                 out, B);
    }
}